// round 4
// baseline (speedup 1.0000x reference)
#include <cuda_runtime.h>

// ---------------------------------------------------------------------------
// SWMSA: shifted-window multi-head self-attention (Swin block attention)
// B=32, H=W=56, WS=7, SS=3, NH=8, E=256, HD=32, NW=64, WD=49
// Stage 1: per-token QKV projection (with shift+window gather on read)
// Stage 2: windowed attention with rel-pos bias + shift mask, online softmax
// Stage 3: output projection GEMM
// ---------------------------------------------------------------------------

#define BNUM 32
#define HW   56
#define WSZ  7
#define SSZ  3
#define NHEAD 8
#define EMB  256
#define HDIM 32
#define NWIN 64
#define WD   49
#define NTOK (HW*HW)              // 3136
#define QKV_PER_WIN (NHEAD*WD*HDIM)   // 12544

// scratch (static device arrays: allowed; no cudaMalloc anywhere)
__device__ __align__(16) float g_Q[(size_t)BNUM*NWIN*QKV_PER_WIN];
__device__ __align__(16) float g_K[(size_t)BNUM*NWIN*QKV_PER_WIN];
__device__ __align__(16) float g_V[(size_t)BNUM*NWIN*QKV_PER_WIN];
__device__ __align__(16) float g_O[(size_t)BNUM*NTOK*EMB];

// ---------------------------------------------------------------------------
// Kernel 1: QKV projection.
// Block = one (batch, window). 256 threads, 8 warps.
// Each warp handles 49 (token,head) pairs in groups of 7; lane owns output
// channel `lane` of each of q/k/v (W columns lane, 32+lane, 64+lane).
// ---------------------------------------------------------------------------
__global__ __launch_bounds__(256) void qkv_kernel(const float* __restrict__ x,
                                                  const float* __restrict__ Wq,
                                                  const float* __restrict__ bq) {
    extern __shared__ float sm[];
    float* xs = sm;                    // 49*256 = 12544 floats
    float* Ws = sm + 12544;            // 32*96  = 3072
    float* bs = sm + 12544 + 3072;     // 96

    int bw = blockIdx.x;
    int b  = bw >> 6, w = bw & 63;
    int wr = w >> 3,  wc = w & 7;
    int tid = threadIdx.x;

    for (int i = tid; i < 32*96; i += 256) Ws[i] = Wq[i];
    if (tid < 96) bs[tid] = bq[tid];

    // gather x window (applies the -SS cyclic shift: shifted (r,c) <- orig (r+3,c+3))
    const float4* x4 = reinterpret_cast<const float4*>(x);
    float4* xs4 = reinterpret_cast<float4*>(xs);
    for (int i = tid; i < WD*64; i += 256) {
        int t = i >> 6, qq = i & 63;
        int tr = t / 7, tc = t - tr*7;
        int row = wr*7 + tr + SSZ; if (row >= HW) row -= HW;
        int col = wc*7 + tc + SSZ; if (col >= HW) col -= HW;
        xs4[i] = x4[((size_t)b*NTOK + row*HW + col)*64 + qq];
    }
    __syncthreads();

    int warp = tid >> 5, lane = tid & 31;
    size_t obase = (size_t)bw * QKV_PER_WIN;

    for (int g = 0; g < 7; ++g) {
        int p0 = warp*49 + g*7;
        float acc0[7], acc1[7], acc2[7];
        int off[7];
#pragma unroll
        for (int i = 0; i < 7; ++i) {
            acc0[i] = acc1[i] = acc2[i] = 0.f;
            int p = p0 + i;
            int t = p >> 3, h = p & 7;
            off[i] = t*EMB + h*HDIM;
        }
#pragma unroll 4
        for (int d = 0; d < 32; ++d) {
            float w0 = Ws[d*96 + lane];          // bank = lane: conflict-free
            float w1 = Ws[d*96 + 32 + lane];
            float w2 = Ws[d*96 + 64 + lane];
#pragma unroll
            for (int i = 0; i < 7; ++i) {
                float a = xs[off[i] + d];        // warp-uniform: broadcast
                acc0[i] += a*w0; acc1[i] += a*w1; acc2[i] += a*w2;
            }
        }
#pragma unroll
        for (int i = 0; i < 7; ++i) {
            int p = p0 + i;
            int t = p >> 3, h = p & 7;
            size_t o = obase + ((size_t)(h*49 + t))*HDIM + lane;
            g_Q[o] = acc0[i] + bs[lane];
            g_K[o] = acc1[i] + bs[32 + lane];
            g_V[o] = acc2[i] + bs[64 + lane];
        }
    }
}

// ---------------------------------------------------------------------------
// Kernel 2: windowed attention.
// Block = one (batch, window), 512 threads = 16 warps = 2 warps per head.
// Lane owns one query row (r = (warp&1)*32 + lane, active if r<49).
// Scores chunked 25+24 with online softmax merge to stay inside 128 regs.
// ---------------------------------------------------------------------------
template<int CNT>
__device__ __forceinline__ void attn_chunk(int j0, const float* Kh, const float* Vh,
        const float* bh, const int* Rg, int myreg,
        const float (&q)[32], float (&o)[32], float& m, float& l) {
    const float4* K4 = reinterpret_cast<const float4*>(Kh);
    const float4* V4 = reinterpret_cast<const float4*>(Vh);
    float s[CNT];
#pragma unroll
    for (int jj = 0; jj < CNT; ++jj) {
        int j = j0 + jj;
        float a = 0.f;
#pragma unroll
        for (int d4 = 0; d4 < 8; ++d4) {
            float4 k4 = K4[j*8 + d4];            // warp-uniform: broadcast
            a += q[d4*4+0]*k4.x; a += q[d4*4+1]*k4.y;
            a += q[d4*4+2]*k4.z; a += q[d4*4+3]*k4.w;
        }
        s[jj] = a*0.17677669529663687f + bh[j]
              + ((Rg[j] == myreg) ? 0.f : -100.f);
    }
    float cm = m;
#pragma unroll
    for (int jj = 0; jj < CNT; ++jj) cm = fmaxf(cm, s[jj]);
    float f = __expf(m - cm);
    l *= f;
#pragma unroll
    for (int d = 0; d < 32; ++d) o[d] *= f;
#pragma unroll
    for (int jj = 0; jj < CNT; ++jj) {
        float p = __expf(s[jj] - cm);
        l += p;
        int j = j0 + jj;
#pragma unroll
        for (int d4 = 0; d4 < 8; ++d4) {
            float4 v4 = V4[j*8 + d4];
            o[d4*4+0] += p*v4.x; o[d4*4+1] += p*v4.y;
            o[d4*4+2] += p*v4.z; o[d4*4+3] += p*v4.w;
        }
    }
    m = cm;
}

__global__ __launch_bounds__(512) void attn_kernel(const float* __restrict__ rpb) {
    extern __shared__ float sm[];
    float* Ks = sm;                          // 8*49*32 = 12544
    float* Vs = sm + 12544;                  // 12544
    float* Bi = sm + 25088;                  // 8*49*49 = 19208
    int*   Rg = reinterpret_cast<int*>(sm + 44296);   // 49 ints

    int bw = blockIdx.x;
    int b  = bw >> 6, w = bw & 63;
    int wr = w >> 3,  wc = w & 7;
    int tid = threadIdx.x;

    {   // stage K,V of all 8 heads into smem
        const float4* gk = reinterpret_cast<const float4*>(g_K + (size_t)bw*QKV_PER_WIN);
        const float4* gv = reinterpret_cast<const float4*>(g_V + (size_t)bw*QKV_PER_WIN);
        float4* ks4 = reinterpret_cast<float4*>(Ks);
        float4* vs4 = reinterpret_cast<float4*>(Vs);
        for (int i = tid; i < QKV_PER_WIN/4; i += 512) { ks4[i] = gk[i]; vs4[i] = gv[i]; }
    }
    // expand relative-position bias table to (head, q, k)
    for (int e = tid; e < NHEAD*WD*WD; e += 512) {
        int h  = e / (WD*WD);
        int r2 = e - h*(WD*WD);
        int i  = r2 / WD;
        int j  = r2 - i*WD;
        int idx = (i/7 - j/7 + 6)*13 + (i%7 - j%7 + 6);
        Bi[e] = rpb[idx*NHEAD + h];
    }
    // shift-mask region ids (regions defined on the SHIFTED image grid)
    if (tid < WD) {
        int rs = wr*7 + tid/7, cs = wc*7 + tid%7;
        int zr = (rs < HW-WSZ) ? 0 : ((rs < HW-SSZ) ? 1 : 2);
        int zc = (cs < HW-WSZ) ? 0 : ((cs < HW-SSZ) ? 1 : 2);
        Rg[tid] = zr*3 + zc;
    }
    __syncthreads();

    int warp = tid >> 5, lane = tid & 31;
    int h = warp >> 1;
    int r = ((warp & 1) << 5) + lane;
    if (r >= WD) return;

    float q[32];
    {
        const float4* q4 = reinterpret_cast<const float4*>(
            g_Q + (size_t)bw*QKV_PER_WIN + (size_t)(h*49 + r)*HDIM);
#pragma unroll
        for (int i = 0; i < 8; ++i) {
            float4 v = q4[i];
            q[i*4+0]=v.x; q[i*4+1]=v.y; q[i*4+2]=v.z; q[i*4+3]=v.w;
        }
    }
    const float* Kh = Ks + h*WD*HDIM;
    const float* Vh = Vs + h*WD*HDIM;
    const float* bh = Bi + h*WD*WD + r*WD;   // bank (17r+j)%32: conflict-free
    int myreg = Rg[r];

    float o[32];
#pragma unroll
    for (int d = 0; d < 32; ++d) o[d] = 0.f;
    float m = -1e30f, l = 0.f;

    attn_chunk<25>(0,  Kh, Vh, bh, Rg, myreg, q, o, m, l);
    attn_chunk<24>(25, Kh, Vh, bh, Rg, myreg, q, o, m, l);

    float inv = 1.f / l;

    // scatter back: shifted (rs,cs) -> original (rs+3, cs+3) mod 56, token-major
    int rs = wr*7 + r/7 + SSZ; if (rs >= HW) rs -= HW;
    int cs = wc*7 + r%7 + SSZ; if (cs >= HW) cs -= HW;
    float4* op4 = reinterpret_cast<float4*>(
        g_O + ((size_t)b*NTOK + rs*HW + cs)*EMB + h*HDIM);
#pragma unroll
    for (int i = 0; i < 8; ++i) {
        float4 v;
        v.x = o[i*4+0]*inv; v.y = o[i*4+1]*inv;
        v.z = o[i*4+2]*inv; v.w = o[i*4+3]*inv;
        op4[i] = v;
    }
}

// ---------------------------------------------------------------------------
// Kernel 3: output projection GEMM.
// C[100352,256] = g_O @ proj_w + proj_b.  64x64x16 tiles, 4x4 micro-tiles.
// ---------------------------------------------------------------------------
__global__ __launch_bounds__(256) void proj_kernel(const float* __restrict__ Wp,
                                                   const float* __restrict__ bp,
                                                   float* __restrict__ out) {
    __shared__ __align__(16) float As[16][64];   // A transposed: As[k][m]
    __shared__ __align__(16) float Bs[16][64];   // Bs[k][n]

    int bm = blockIdx.x;       // 0..1567
    int bn = blockIdx.y;       // 0..3
    int tid = threadIdx.x;
    int tx = tid & 15, ty = tid >> 4;

    float acc[4][4];
#pragma unroll
    for (int i = 0; i < 4; ++i)
#pragma unroll
        for (int j = 0; j < 4; ++j) acc[i][j] = 0.f;

    const float* Ab = g_O + (size_t)bm*64*EMB;
    int arow = tid >> 2, acol = (tid & 3) * 4;
    int brow = tid >> 4, bcol = (tid & 15) * 4;

    for (int kb = 0; kb < EMB; kb += 16) {
        float4 a = *reinterpret_cast<const float4*>(Ab + (size_t)arow*EMB + kb + acol);
        As[acol+0][arow] = a.x; As[acol+1][arow] = a.y;
        As[acol+2][arow] = a.z; As[acol+3][arow] = a.w;
        float4 bv = *reinterpret_cast<const float4*>(Wp + (size_t)(kb+brow)*EMB + bn*64 + bcol);
        *reinterpret_cast<float4*>(&Bs[brow][bcol]) = bv;
        __syncthreads();
#pragma unroll
        for (int k = 0; k < 16; ++k) {
            float4 a4 = *reinterpret_cast<const float4*>(&As[k][ty*4]);
            float4 b4 = *reinterpret_cast<const float4*>(&Bs[k][tx*4]);
            float av[4] = {a4.x, a4.y, a4.z, a4.w};
            float bw4[4] = {b4.x, b4.y, b4.z, b4.w};
#pragma unroll
            for (int i = 0; i < 4; ++i)
#pragma unroll
                for (int j = 0; j < 4; ++j)
                    acc[i][j] += av[i]*bw4[j];
        }
        __syncthreads();
    }

    float4 bias4 = *reinterpret_cast<const float4*>(bp + bn*64 + tx*4);
    float bb[4] = {bias4.x, bias4.y, bias4.z, bias4.w};
#pragma unroll
    for (int i = 0; i < 4; ++i) {
        size_t mrow = (size_t)bm*64 + ty*4 + i;
        float4 v;
        v.x = acc[i][0]+bb[0]; v.y = acc[i][1]+bb[1];
        v.z = acc[i][2]+bb[2]; v.w = acc[i][3]+bb[3];
        *reinterpret_cast<float4*>(out + mrow*EMB + bn*64 + tx*4) = v;
    }
}

// ---------------------------------------------------------------------------
extern "C" void kernel_launch(void* const* d_in, const int* in_sizes, int n_in,
                              void* d_out, int out_size) {
    const float* x      = (const float*)d_in[0];
    const float* qkv_w  = (const float*)d_in[1];
    const float* qkv_b  = (const float*)d_in[2];
    const float* proj_w = (const float*)d_in[3];
    const float* proj_b = (const float*)d_in[4];
    const float* rpb    = (const float*)d_in[5];
    float* out = (float*)d_out;

    const int qkv_smem  = (12544 + 3072 + 96) * 4;      // 62,848 B
    const int attn_smem = (44296 + 64) * 4;             // 177,440 B

    cudaFuncSetAttribute(qkv_kernel,  cudaFuncAttributeMaxDynamicSharedMemorySize, qkv_smem);
    cudaFuncSetAttribute(attn_kernel, cudaFuncAttributeMaxDynamicSharedMemorySize, attn_smem);

    qkv_kernel<<<BNUM*NWIN, 256, qkv_smem>>>(x, qkv_w, qkv_b);
    attn_kernel<<<BNUM*NWIN, 512, attn_smem>>>(rpb);
    dim3 grid(BNUM*NTOK/64, EMB/64);
    proj_kernel<<<grid, 256>>>(proj_w, proj_b, out);
}

// round 6
// speedup vs baseline: 1.2698x; 1.2698x over previous
#include <cuda_runtime.h>

// ---------------------------------------------------------------------------
// SWMSA: shifted-window multi-head self-attention (Swin block attention)
// B=32, H=W=56, WS=7, SS=3, NH=8, E=256, HD=32, NW=64, WD=49
// Stage 1: per-token QKV projection (with shift+window gather on read)  [fp32]
// Stage 2: windowed attention, rel-pos bias + shift mask, online softmax [fp32]
// Stage 3: output projection GEMM                                  [TF32 MMA]
// ---------------------------------------------------------------------------

#define BNUM 32
#define HW   56
#define WSZ  7
#define SSZ  3
#define NHEAD 8
#define EMB  256
#define HDIM 32
#define NWIN 64
#define WD   49
#define NTOK (HW*HW)              // 3136
#define QKV_PER_WIN (NHEAD*WD*HDIM)   // 12544

// scratch (static device arrays: allowed; no cudaMalloc anywhere)
__device__ __align__(16) float g_Q[(size_t)BNUM*NWIN*QKV_PER_WIN];
__device__ __align__(16) float g_K[(size_t)BNUM*NWIN*QKV_PER_WIN];
__device__ __align__(16) float g_V[(size_t)BNUM*NWIN*QKV_PER_WIN];
__device__ __align__(16) float g_O[(size_t)BNUM*NTOK*EMB];

// ---------------------------------------------------------------------------
// Kernel 1: QKV projection. (unchanged from R4 — 180us, near issue bound)
// ---------------------------------------------------------------------------
__global__ __launch_bounds__(256) void qkv_kernel(const float* __restrict__ x,
                                                  const float* __restrict__ Wq,
                                                  const float* __restrict__ bq) {
    extern __shared__ float sm[];
    float* xs = sm;                    // 49*256 = 12544 floats
    float* Ws = sm + 12544;            // 32*96  = 3072
    float* bs = sm + 12544 + 3072;     // 96

    int bw = blockIdx.x;
    int b  = bw >> 6, w = bw & 63;
    int wr = w >> 3,  wc = w & 7;
    int tid = threadIdx.x;

    for (int i = tid; i < 32*96; i += 256) Ws[i] = Wq[i];
    if (tid < 96) bs[tid] = bq[tid];

    const float4* x4 = reinterpret_cast<const float4*>(x);
    float4* xs4 = reinterpret_cast<float4*>(xs);
    for (int i = tid; i < WD*64; i += 256) {
        int t = i >> 6, qq = i & 63;
        int tr = t / 7, tc = t - tr*7;
        int row = wr*7 + tr + SSZ; if (row >= HW) row -= HW;
        int col = wc*7 + tc + SSZ; if (col >= HW) col -= HW;
        xs4[i] = x4[((size_t)b*NTOK + row*HW + col)*64 + qq];
    }
    __syncthreads();

    int warp = tid >> 5, lane = tid & 31;
    size_t obase = (size_t)bw * QKV_PER_WIN;

    for (int g = 0; g < 7; ++g) {
        int p0 = warp*49 + g*7;
        float acc0[7], acc1[7], acc2[7];
        int off[7];
#pragma unroll
        for (int i = 0; i < 7; ++i) {
            acc0[i] = acc1[i] = acc2[i] = 0.f;
            int p = p0 + i;
            int t = p >> 3, h = p & 7;
            off[i] = t*EMB + h*HDIM;
        }
#pragma unroll 4
        for (int d = 0; d < 32; ++d) {
            float w0 = Ws[d*96 + lane];
            float w1 = Ws[d*96 + 32 + lane];
            float w2 = Ws[d*96 + 64 + lane];
#pragma unroll
            for (int i = 0; i < 7; ++i) {
                float a = xs[off[i] + d];
                acc0[i] += a*w0; acc1[i] += a*w1; acc2[i] += a*w2;
            }
        }
#pragma unroll
        for (int i = 0; i < 7; ++i) {
            int p = p0 + i;
            int t = p >> 3, h = p & 7;
            size_t o = obase + ((size_t)(h*49 + t))*HDIM + lane;
            g_Q[o] = acc0[i] + bs[lane];
            g_K[o] = acc1[i] + bs[32 + lane];
            g_V[o] = acc2[i] + bs[64 + lane];
        }
    }
}

// ---------------------------------------------------------------------------
// Kernel 2: windowed attention. (unchanged from R4)
// ---------------------------------------------------------------------------
template<int CNT>
__device__ __forceinline__ void attn_chunk(int j0, const float* Kh, const float* Vh,
        const float* bh, const int* Rg, int myreg,
        const float (&q)[32], float (&o)[32], float& m, float& l) {
    const float4* K4 = reinterpret_cast<const float4*>(Kh);
    const float4* V4 = reinterpret_cast<const float4*>(Vh);
    float s[CNT];
#pragma unroll
    for (int jj = 0; jj < CNT; ++jj) {
        int j = j0 + jj;
        float a = 0.f;
#pragma unroll
        for (int d4 = 0; d4 < 8; ++d4) {
            float4 k4 = K4[j*8 + d4];
            a += q[d4*4+0]*k4.x; a += q[d4*4+1]*k4.y;
            a += q[d4*4+2]*k4.z; a += q[d4*4+3]*k4.w;
        }
        s[jj] = a*0.17677669529663687f + bh[j]
              + ((Rg[j] == myreg) ? 0.f : -100.f);
    }
    float cm = m;
#pragma unroll
    for (int jj = 0; jj < CNT; ++jj) cm = fmaxf(cm, s[jj]);
    float f = __expf(m - cm);
    l *= f;
#pragma unroll
    for (int d = 0; d < 32; ++d) o[d] *= f;
#pragma unroll
    for (int jj = 0; jj < CNT; ++jj) {
        float p = __expf(s[jj] - cm);
        l += p;
        int j = j0 + jj;
#pragma unroll
        for (int d4 = 0; d4 < 8; ++d4) {
            float4 v4 = V4[j*8 + d4];
            o[d4*4+0] += p*v4.x; o[d4*4+1] += p*v4.y;
            o[d4*4+2] += p*v4.z; o[d4*4+3] += p*v4.w;
        }
    }
    m = cm;
}

__global__ __launch_bounds__(512) void attn_kernel(const float* __restrict__ rpb) {
    extern __shared__ float sm[];
    float* Ks = sm;                          // 8*49*32 = 12544
    float* Vs = sm + 12544;                  // 12544
    float* Bi = sm + 25088;                  // 8*49*49 = 19208
    int*   Rg = reinterpret_cast<int*>(sm + 44296);   // 49 ints

    int bw = blockIdx.x;
    int b  = bw >> 6, w = bw & 63;
    int wr = w >> 3,  wc = w & 7;
    int tid = threadIdx.x;

    {
        const float4* gk = reinterpret_cast<const float4*>(g_K + (size_t)bw*QKV_PER_WIN);
        const float4* gv = reinterpret_cast<const float4*>(g_V + (size_t)bw*QKV_PER_WIN);
        float4* ks4 = reinterpret_cast<float4*>(Ks);
        float4* vs4 = reinterpret_cast<float4*>(Vs);
        for (int i = tid; i < QKV_PER_WIN/4; i += 512) { ks4[i] = gk[i]; vs4[i] = gv[i]; }
    }
    for (int e = tid; e < NHEAD*WD*WD; e += 512) {
        int h  = e / (WD*WD);
        int r2 = e - h*(WD*WD);
        int i  = r2 / WD;
        int j  = r2 - i*WD;
        int idx = (i/7 - j/7 + 6)*13 + (i%7 - j%7 + 6);
        Bi[e] = rpb[idx*NHEAD + h];
    }
    if (tid < WD) {
        int rs = wr*7 + tid/7, cs = wc*7 + tid%7;
        int zr = (rs < HW-WSZ) ? 0 : ((rs < HW-SSZ) ? 1 : 2);
        int zc = (cs < HW-WSZ) ? 0 : ((cs < HW-SSZ) ? 1 : 2);
        Rg[tid] = zr*3 + zc;
    }
    __syncthreads();

    int warp = tid >> 5, lane = tid & 31;
    int h = warp >> 1;
    int r = ((warp & 1) << 5) + lane;
    if (r >= WD) return;

    float q[32];
    {
        const float4* q4 = reinterpret_cast<const float4*>(
            g_Q + (size_t)bw*QKV_PER_WIN + (size_t)(h*49 + r)*HDIM);
#pragma unroll
        for (int i = 0; i < 8; ++i) {
            float4 v = q4[i];
            q[i*4+0]=v.x; q[i*4+1]=v.y; q[i*4+2]=v.z; q[i*4+3]=v.w;
        }
    }
    const float* Kh = Ks + h*WD*HDIM;
    const float* Vh = Vs + h*WD*HDIM;
    const float* bh = Bi + h*WD*WD + r*WD;
    int myreg = Rg[r];

    float o[32];
#pragma unroll
    for (int d = 0; d < 32; ++d) o[d] = 0.f;
    float m = -1e30f, l = 0.f;

    attn_chunk<25>(0,  Kh, Vh, bh, Rg, myreg, q, o, m, l);
    attn_chunk<24>(25, Kh, Vh, bh, Rg, myreg, q, o, m, l);

    float inv = 1.f / l;

    int rs = wr*7 + r/7 + SSZ; if (rs >= HW) rs -= HW;
    int cs = wc*7 + r%7 + SSZ; if (cs >= HW) cs -= HW;
    float4* op4 = reinterpret_cast<float4*>(
        g_O + ((size_t)b*NTOK + rs*HW + cs)*EMB + h*HDIM);
#pragma unroll
    for (int i = 0; i < 8; ++i) {
        float4 v;
        v.x = o[i*4+0]*inv; v.y = o[i*4+1]*inv;
        v.z = o[i*4+2]*inv; v.w = o[i*4+3]*inv;
        op4[i] = v;
    }
}

// ---------------------------------------------------------------------------
// Kernel 3: output projection GEMM, TF32 tensor-core version.
// C[100352,256] = g_O @ proj_w + proj_b.
// Block tile 128x128, 256 threads = 8 warps (2 in M x 4 in N).
// Warp tile 64x32 = 4x4 mma.m16n8k8 tiles. fp32 accumulate, rna-rounded tf32.
// Smem stride 136 words -> frag-load bank pattern (8t+g)%32: conflict-free.
// ---------------------------------------------------------------------------
__device__ __forceinline__ unsigned f2tf32(float f) {
    unsigned r;
    asm("cvt.rna.tf32.f32 %0, %1;" : "=r"(r) : "f"(f));
    return r;
}

__device__ __forceinline__ void mma_tf32(float* c, unsigned a0, unsigned a1,
                                         unsigned a2, unsigned a3,
                                         unsigned b0, unsigned b1) {
    asm volatile(
        "mma.sync.aligned.m16n8k8.row.col.f32.tf32.tf32.f32 "
        "{%0,%1,%2,%3}, {%4,%5,%6,%7}, {%8,%9}, {%0,%1,%2,%3};\n"
        : "+f"(c[0]), "+f"(c[1]), "+f"(c[2]), "+f"(c[3])
        : "r"(a0), "r"(a1), "r"(a2), "r"(a3), "r"(b0), "r"(b1));
}

__global__ __launch_bounds__(256) void proj_kernel(const float* __restrict__ Wp,
                                                   const float* __restrict__ bp,
                                                   float* __restrict__ out) {
    __shared__ unsigned As[32][136];   // A^T: As[k][m] (tf32 bits)
    __shared__ unsigned Bs[32][136];   // Bs[k][n]

    int bm = blockIdx.x;               // 0..783
    int bn = blockIdx.y;               // 0..1
    int tid = threadIdx.x;
    int warp = tid >> 5, lane = tid & 31;
    int g = lane >> 2, t = lane & 3;   // octet group / thread-in-group

    int wm = (warp & 1) * 64;          // warp M offset (2 warps in M)
    int wn = (warp >> 1) * 32;         // warp N offset (4 warps in N)

    float acc[4][4][4];
#pragma unroll
    for (int mi = 0; mi < 4; ++mi)
#pragma unroll
        for (int ni = 0; ni < 4; ++ni)
#pragma unroll
            for (int rr = 0; rr < 4; ++rr) acc[mi][ni][rr] = 0.f;

    const float* Ag = g_O + (size_t)bm * 128 * EMB;
    int ar = tid >> 1, ac = (tid & 1) * 16;     // A: 2 threads/row, 16 floats each
    int br = tid >> 3, bc = (tid & 7) * 16;     // B: 8 threads/row, 16 floats each

    for (int kb = 0; kb < EMB; kb += 32) {
        // stage A (transpose into As[k][m], convert to tf32)
#pragma unroll
        for (int i = 0; i < 4; ++i) {
            float4 v = *reinterpret_cast<const float4*>(Ag + (size_t)ar*EMB + kb + ac + i*4);
            As[ac + i*4 + 0][ar] = f2tf32(v.x);
            As[ac + i*4 + 1][ar] = f2tf32(v.y);
            As[ac + i*4 + 2][ar] = f2tf32(v.z);
            As[ac + i*4 + 3][ar] = f2tf32(v.w);
        }
        // stage B (row-major [k][n], convert to tf32)
#pragma unroll
        for (int i = 0; i < 4; ++i) {
            float4 v = *reinterpret_cast<const float4*>(Wp + (size_t)(kb + br)*EMB + bn*128 + bc + i*4);
            uint4 u;
            u.x = f2tf32(v.x); u.y = f2tf32(v.y);
            u.z = f2tf32(v.z); u.w = f2tf32(v.w);
            *reinterpret_cast<uint4*>(&Bs[br][bc + i*4]) = u;
        }
        __syncthreads();

#pragma unroll
        for (int ks = 0; ks < 4; ++ks) {
            int k0 = ks * 8;
            unsigned af[4][4];
#pragma unroll
            for (int mi = 0; mi < 4; ++mi) {
                int m0 = wm + mi*16;
                af[mi][0] = As[k0 + t    ][m0 + g    ];
                af[mi][1] = As[k0 + t    ][m0 + g + 8];
                af[mi][2] = As[k0 + t + 4][m0 + g    ];
                af[mi][3] = As[k0 + t + 4][m0 + g + 8];
            }
            unsigned bf[4][2];
#pragma unroll
            for (int ni = 0; ni < 4; ++ni) {
                int n0 = wn + ni*8;
                bf[ni][0] = Bs[k0 + t    ][n0 + g];
                bf[ni][1] = Bs[k0 + t + 4][n0 + g];
            }
#pragma unroll
            for (int mi = 0; mi < 4; ++mi)
#pragma unroll
                for (int ni = 0; ni < 4; ++ni)
                    mma_tf32(acc[mi][ni], af[mi][0], af[mi][1], af[mi][2], af[mi][3],
                             bf[ni][0], bf[ni][1]);
        }
        __syncthreads();
    }

    // epilogue: c0/c1 -> (row g, cols 2t,2t+1); c2/c3 -> row g+8
#pragma unroll
    for (int ni = 0; ni < 4; ++ni) {
        int n = bn*128 + wn + ni*8 + 2*t;
        float2 bb = *reinterpret_cast<const float2*>(bp + n);
#pragma unroll
        for (int mi = 0; mi < 4; ++mi) {
            size_t m = (size_t)bm*128 + wm + mi*16;
            float2 v0, v1;
            v0.x = acc[mi][ni][0] + bb.x; v0.y = acc[mi][ni][1] + bb.y;
            v1.x = acc[mi][ni][2] + bb.x; v1.y = acc[mi][ni][3] + bb.y;
            *reinterpret_cast<float2*>(out + (m + g    )*EMB + n) = v0;
            *reinterpret_cast<float2*>(out + (m + g + 8)*EMB + n) = v1;
        }
    }
}

// ---------------------------------------------------------------------------
extern "C" void kernel_launch(void* const* d_in, const int* in_sizes, int n_in,
                              void* d_out, int out_size) {
    const float* x      = (const float*)d_in[0];
    const float* qkv_w  = (const float*)d_in[1];
    const float* qkv_b  = (const float*)d_in[2];
    const float* proj_w = (const float*)d_in[3];
    const float* proj_b = (const float*)d_in[4];
    const float* rpb    = (const float*)d_in[5];
    float* out = (float*)d_out;

    const int qkv_smem  = (12544 + 3072 + 96) * 4;      // 62,848 B
    const int attn_smem = (44296 + 64) * 4;             // 177,440 B

    cudaFuncSetAttribute(qkv_kernel,  cudaFuncAttributeMaxDynamicSharedMemorySize, qkv_smem);
    cudaFuncSetAttribute(attn_kernel, cudaFuncAttributeMaxDynamicSharedMemorySize, attn_smem);

    qkv_kernel<<<BNUM*NWIN, 256, qkv_smem>>>(x, qkv_w, qkv_b);
    attn_kernel<<<BNUM*NWIN, 512, attn_smem>>>(rpb);
    dim3 grid(BNUM*NTOK/128, EMB/128);
    proj_kernel<<<grid, 256>>>(proj_w, proj_b, out);
}

// round 7
// speedup vs baseline: 1.3679x; 1.0772x over previous
#include <cuda_runtime.h>

// ---------------------------------------------------------------------------
// SWMSA: shifted-window multi-head self-attention (Swin block attention)
// B=32, H=W=56, WS=7, SS=3, NH=8, E=256, HD=32, NW=64, WD=49
// Kernel A: one-shot rel-pos-bias expansion (identical for every window)
// Kernel B: fused QKV-projection + windowed attention (all in smem/regs)
// Kernel C: output projection GEMM [TF32 MMA]
// ---------------------------------------------------------------------------

#define BNUM 32
#define HW   56
#define NHEAD 8
#define EMB  256
#define HDIM 32
#define NWIN 64
#define WD   49
#define NTOK (HW*HW)              // 3136

// scratch (static device arrays: allowed; no cudaMalloc anywhere)
__device__ __align__(16) float g_O [(size_t)BNUM*NTOK*EMB];
__device__ __align__(16) float g_Bi[NHEAD*WD*WD];     // 19208 floats

// ---------------------------------------------------------------------------
// Kernel A: expand rpb table -> (head, q, k) bias, once per launch.
// ---------------------------------------------------------------------------
__global__ __launch_bounds__(512) void bias_kernel(const float* __restrict__ rpb) {
    int i = blockIdx.x * 512 + threadIdx.x;
    if (i >= NHEAD*WD*WD) return;
    int h  = i / (WD*WD);
    int r2 = i - h*(WD*WD);
    int a  = r2 / WD;
    int bb = r2 - a*WD;
    int idx = (a/7 - bb/7 + 6)*13 + (a%7 - bb%7 + 6);
    g_Bi[i] = rpb[idx*NHEAD + h];
}

// ---------------------------------------------------------------------------
// Fused kernel smem layout (floats):
//   Ks  @ 0      : 8*49*32 = 12544
//   Vs  @ 12544  : 12544
//   C   @ 25088  : 19208   (phase 1-2: x window, padded stride 260; phase 3+: Bi)
//   Rg  @ 44296  : 64 (ints)
//   Ws  @ 44360  : 32*96 = 3072
//   bs  @ 47432  : 96
//   total 47528 floats = 190,112 B  (1 block/SM)
// ---------------------------------------------------------------------------
#define OFF_VS 12544
#define OFF_C  25088
#define OFF_RG 44296
#define OFF_WS 44360
#define OFF_BS 47432
#define SMEM_FLOATS 47528
#define XS_STRIDE 260            // padded token row (65 float4; 65 % 8 == 1)

template<int CNT>
__device__ __forceinline__ void attn_chunk(int j0, const float* Kh, const float* Vh,
        const float* bh, const int* Rg, int myreg,
        const float (&q)[32], float (&o)[32], float& m, float& l) {
    const float4* K4 = reinterpret_cast<const float4*>(Kh);
    const float4* V4 = reinterpret_cast<const float4*>(Vh);
    float s[CNT];
#pragma unroll
    for (int jj = 0; jj < CNT; ++jj) {
        int j = j0 + jj;
        float a = 0.f;
#pragma unroll
        for (int d4 = 0; d4 < 8; ++d4) {
            float4 k4 = K4[j*8 + d4];              // warp-uniform: broadcast
            a += q[d4*4+0]*k4.x; a += q[d4*4+1]*k4.y;
            a += q[d4*4+2]*k4.z; a += q[d4*4+3]*k4.w;
        }
        s[jj] = a*0.17677669529663687f + bh[j]
              + ((Rg[j] == myreg) ? 0.f : -100.f);
    }
    float cm = m;
#pragma unroll
    for (int jj = 0; jj < CNT; ++jj) cm = fmaxf(cm, s[jj]);
    float f = __expf(m - cm);
    l *= f;
#pragma unroll
    for (int d = 0; d < 32; ++d) o[d] *= f;
#pragma unroll
    for (int jj = 0; jj < CNT; ++jj) {
        float p = __expf(s[jj] - cm);
        l += p;
        int j = j0 + jj;
#pragma unroll
        for (int d4 = 0; d4 < 8; ++d4) {
            float4 v4 = V4[j*8 + d4];
            o[d4*4+0] += p*v4.x; o[d4*4+1] += p*v4.y;
            o[d4*4+2] += p*v4.z; o[d4*4+3] += p*v4.w;
        }
    }
    m = cm;
}

__global__ __launch_bounds__(512) void fused_kernel(const float* __restrict__ x,
                                                    const float* __restrict__ Wq,
                                                    const float* __restrict__ bq) {
    extern __shared__ float sm[];
    float* Ks = sm;
    float* Vs = sm + OFF_VS;
    float* C  = sm + OFF_C;
    int*   Rg = reinterpret_cast<int*>(sm + OFF_RG);
    float* Ws = sm + OFF_WS;
    float* bs = sm + OFF_BS;

    int bw = blockIdx.x;
    int b  = bw >> 6, w = bw & 63;
    int wr = w >> 3,  wc = w & 7;
    int tid = threadIdx.x, warp = tid >> 5, lane = tid & 31;

    // stage weights + bias
    for (int i = tid; i < 32*96; i += 512) Ws[i] = Wq[i];
    if (tid < 96) bs[tid] = bq[tid];

    // phase 1: gather shifted x window into C (padded stride 260 floats)
    const float4* x4 = reinterpret_cast<const float4*>(x);
    float4* xs4 = reinterpret_cast<float4*>(C);
    for (int i = tid; i < WD*64; i += 512) {
        int t = i >> 6, qq = i & 63;
        int tr = t / 7, tc = t - tr*7;
        int row = wr*7 + tr + 3; if (row >= HW) row -= HW;
        int col = wc*7 + tc + 3; if (col >= HW) col -= HW;
        xs4[t*65 + qq] = x4[((size_t)b*NTOK + row*HW + col)*64 + qq];
    }
    __syncthreads();

    // phase 2a: K,V projection into smem. 16 warps x 25 (token,head) pairs,
    // lane owns output channel `lane` (W columns 32+lane / 64+lane: bank=lane).
    {
        float a1[25], a2[25];
        int off[25];
#pragma unroll
        for (int i = 0; i < 25; ++i) {
            int p = warp*25 + i;
            int t = p >> 3; if (t > 48) t = 48;   // clamp dead pairs (warp 15)
            int h = p & 7;
            off[i] = t*XS_STRIDE + h*HDIM;
            a1[i] = 0.f; a2[i] = 0.f;
        }
        for (int d = 0; d < 32; ++d) {
            float w1 = Ws[d*96 + 32 + lane];
            float w2 = Ws[d*96 + 64 + lane];
#pragma unroll
            for (int i = 0; i < 25; ++i) {
                float a = C[off[i] + d];           // warp-uniform: broadcast
                a1[i] += a*w1; a2[i] += a*w2;
            }
        }
        float bk = bs[32 + lane], bv = bs[64 + lane];
#pragma unroll
        for (int i = 0; i < 25; ++i) {
            int p = warp*25 + i;
            if (p < NHEAD*WD) {
                int t = p >> 3, h = p & 7;
                int o = (h*WD + t)*HDIM + lane;    // bank = lane
                Ks[o] = a1[i] + bk;
                Vs[o] = a2[i] + bv;
            }
        }
    }

    // phase 2b: each attention thread computes its own q row in registers.
    int h = warp >> 1;
    int r = ((warp & 1) << 5) + lane;
    float q[32];
    if (r < WD) {
        float xr[32];
        const float4* xrow = reinterpret_cast<const float4*>(C) + r*65 + h*8;
#pragma unroll
        for (int i = 0; i < 8; ++i) {              // 65%8==1 -> conflict-free
            float4 v = xrow[i];
            xr[i*4]=v.x; xr[i*4+1]=v.y; xr[i*4+2]=v.z; xr[i*4+3]=v.w;
        }
#pragma unroll
        for (int d = 0; d < 32; ++d) q[d] = bs[d];
        for (int k = 0; k < 32; ++k) {
#pragma unroll
            for (int d4 = 0; d4 < 8; ++d4) {
                float4 wv = *reinterpret_cast<const float4*>(&Ws[k*96 + d4*4]);
                q[d4*4+0] += xr[k]*wv.x;
                q[d4*4+1] += xr[k]*wv.y;
                q[d4*4+2] += xr[k]*wv.z;
                q[d4*4+3] += xr[k]*wv.w;
            }
        }
    }
    __syncthreads();   // all reads of x window done

    // phase 3: overwrite C with precomputed bias; compute region ids.
    {
        const float4* gb = reinterpret_cast<const float4*>(g_Bi);
        float4* c4 = reinterpret_cast<float4*>(C);
        for (int i = tid; i < (NHEAD*WD*WD)/4; i += 512) c4[i] = gb[i];
    }
    if (tid < WD) {
        int rs = wr*7 + tid/7, cs = wc*7 + tid%7;
        int zr = (rs < 49) ? 0 : ((rs < 53) ? 1 : 2);
        int zc = (cs < 49) ? 0 : ((cs < 53) ? 1 : 2);
        Rg[tid] = zr*3 + zc;
    }
    __syncthreads();

    if (r >= WD) return;

    // phase 4: attention (online softmax, 25+24 chunks)
    const float* Kh = Ks + h*WD*HDIM;
    const float* Vh = Vs + h*WD*HDIM;
    const float* bh = C + h*WD*WD + r*WD;
    int myreg = Rg[r];

    float o[32];
#pragma unroll
    for (int d = 0; d < 32; ++d) o[d] = 0.f;
    float m = -1e30f, l = 0.f;

    attn_chunk<25>(0,  Kh, Vh, bh, Rg, myreg, q, o, m, l);
    attn_chunk<24>(25, Kh, Vh, bh, Rg, myreg, q, o, m, l);

    float inv = 1.f / l;

    // scatter back: shifted (rs,cs) -> original (rs+3, cs+3) mod 56
    int rs = wr*7 + r/7 + 3; if (rs >= HW) rs -= HW;
    int cs = wc*7 + r%7 + 3; if (cs >= HW) cs -= HW;
    float4* op4 = reinterpret_cast<float4*>(
        g_O + ((size_t)b*NTOK + rs*HW + cs)*EMB + h*HDIM);
#pragma unroll
    for (int i = 0; i < 8; ++i) {
        float4 v;
        v.x = o[i*4+0]*inv; v.y = o[i*4+1]*inv;
        v.z = o[i*4+2]*inv; v.w = o[i*4+3]*inv;
        op4[i] = v;
    }
}

// ---------------------------------------------------------------------------
// Kernel C: output projection GEMM, TF32 tensor-core version (unchanged R5).
// ---------------------------------------------------------------------------
__device__ __forceinline__ unsigned f2tf32(float f) {
    unsigned r;
    asm("cvt.rna.tf32.f32 %0, %1;" : "=r"(r) : "f"(f));
    return r;
}

__device__ __forceinline__ void mma_tf32(float* c, unsigned a0, unsigned a1,
                                         unsigned a2, unsigned a3,
                                         unsigned b0, unsigned b1) {
    asm volatile(
        "mma.sync.aligned.m16n8k8.row.col.f32.tf32.tf32.f32 "
        "{%0,%1,%2,%3}, {%4,%5,%6,%7}, {%8,%9}, {%0,%1,%2,%3};\n"
        : "+f"(c[0]), "+f"(c[1]), "+f"(c[2]), "+f"(c[3])
        : "r"(a0), "r"(a1), "r"(a2), "r"(a3), "r"(b0), "r"(b1));
}

__global__ __launch_bounds__(256) void proj_kernel(const float* __restrict__ Wp,
                                                   const float* __restrict__ bp,
                                                   float* __restrict__ out) {
    __shared__ unsigned As[32][136];   // A^T: As[k][m] (tf32 bits)
    __shared__ unsigned Bs[32][136];   // Bs[k][n]

    int bm = blockIdx.x;               // 0..783
    int bn = blockIdx.y;               // 0..1
    int tid = threadIdx.x;
    int warp = tid >> 5, lane = tid & 31;
    int g = lane >> 2, t = lane & 3;

    int wm = (warp & 1) * 64;
    int wn = (warp >> 1) * 32;

    float acc[4][4][4];
#pragma unroll
    for (int mi = 0; mi < 4; ++mi)
#pragma unroll
        for (int ni = 0; ni < 4; ++ni)
#pragma unroll
            for (int rr = 0; rr < 4; ++rr) acc[mi][ni][rr] = 0.f;

    const float* Ag = g_O + (size_t)bm * 128 * EMB;
    int ar = tid >> 1, ac = (tid & 1) * 16;
    int br = tid >> 3, bc = (tid & 7) * 16;

    for (int kb = 0; kb < EMB; kb += 32) {
#pragma unroll
        for (int i = 0; i < 4; ++i) {
            float4 v = *reinterpret_cast<const float4*>(Ag + (size_t)ar*EMB + kb + ac + i*4);
            As[ac + i*4 + 0][ar] = f2tf32(v.x);
            As[ac + i*4 + 1][ar] = f2tf32(v.y);
            As[ac + i*4 + 2][ar] = f2tf32(v.z);
            As[ac + i*4 + 3][ar] = f2tf32(v.w);
        }
#pragma unroll
        for (int i = 0; i < 4; ++i) {
            float4 v = *reinterpret_cast<const float4*>(Wp + (size_t)(kb + br)*EMB + bn*128 + bc + i*4);
            uint4 u;
            u.x = f2tf32(v.x); u.y = f2tf32(v.y);
            u.z = f2tf32(v.z); u.w = f2tf32(v.w);
            *reinterpret_cast<uint4*>(&Bs[br][bc + i*4]) = u;
        }
        __syncthreads();

#pragma unroll
        for (int ks = 0; ks < 4; ++ks) {
            int k0 = ks * 8;
            unsigned af[4][4];
#pragma unroll
            for (int mi = 0; mi < 4; ++mi) {
                int m0 = wm + mi*16;
                af[mi][0] = As[k0 + t    ][m0 + g    ];
                af[mi][1] = As[k0 + t    ][m0 + g + 8];
                af[mi][2] = As[k0 + t + 4][m0 + g    ];
                af[mi][3] = As[k0 + t + 4][m0 + g + 8];
            }
            unsigned bf[4][2];
#pragma unroll
            for (int ni = 0; ni < 4; ++ni) {
                int n0 = wn + ni*8;
                bf[ni][0] = Bs[k0 + t    ][n0 + g];
                bf[ni][1] = Bs[k0 + t + 4][n0 + g];
            }
#pragma unroll
            for (int mi = 0; mi < 4; ++mi)
#pragma unroll
                for (int ni = 0; ni < 4; ++ni)
                    mma_tf32(acc[mi][ni], af[mi][0], af[mi][1], af[mi][2], af[mi][3],
                             bf[ni][0], bf[ni][1]);
        }
        __syncthreads();
    }

#pragma unroll
    for (int ni = 0; ni < 4; ++ni) {
        int n = bn*128 + wn + ni*8 + 2*t;
        float2 bb = *reinterpret_cast<const float2*>(bp + n);
#pragma unroll
        for (int mi = 0; mi < 4; ++mi) {
            size_t m = (size_t)bm*128 + wm + mi*16;
            float2 v0, v1;
            v0.x = acc[mi][ni][0] + bb.x; v0.y = acc[mi][ni][1] + bb.y;
            v1.x = acc[mi][ni][2] + bb.x; v1.y = acc[mi][ni][3] + bb.y;
            *reinterpret_cast<float2*>(out + (m + g    )*EMB + n) = v0;
            *reinterpret_cast<float2*>(out + (m + g + 8)*EMB + n) = v1;
        }
    }
}

// ---------------------------------------------------------------------------
extern "C" void kernel_launch(void* const* d_in, const int* in_sizes, int n_in,
                              void* d_out, int out_size) {
    const float* x      = (const float*)d_in[0];
    const float* qkv_w  = (const float*)d_in[1];
    const float* qkv_b  = (const float*)d_in[2];
    const float* proj_w = (const float*)d_in[3];
    const float* proj_b = (const float*)d_in[4];
    const float* rpb    = (const float*)d_in[5];
    float* out = (float*)d_out;

    const int fused_smem = SMEM_FLOATS * 4;    // 190,112 B
    cudaFuncSetAttribute(fused_kernel, cudaFuncAttributeMaxDynamicSharedMemorySize, fused_smem);

    bias_kernel<<<(NHEAD*WD*WD + 511)/512, 512>>>(rpb);
    fused_kernel<<<BNUM*NWIN, 512, fused_smem>>>(x, qkv_w, qkv_b);
    dim3 grid(BNUM*NTOK/128, EMB/128);
    proj_kernel<<<grid, 256>>>(proj_w, proj_b, out);
}

// round 8
// speedup vs baseline: 2.3514x; 1.7190x over previous
#include <cuda_runtime.h>

// ---------------------------------------------------------------------------
// SWMSA: shifted-window multi-head self-attention (Swin block attention)
// B=32, H=W=56, WS=7, SS=3, NH=8, E=256, HD=32, NW=64, WD=49
// Kernel A: one-shot rel-pos-bias expansion
// Kernel B: fully tensor-core fused QKV + attention (TF32 mma throughout)
// Kernel C: output projection GEMM [TF32 MMA]
// ---------------------------------------------------------------------------

#define BNUM 32
#define HW   56
#define NHEAD 8
#define EMB  256
#define HDIM 32
#define NWIN 64
#define WD   49
#define NTOK (HW*HW)              // 3136

__device__ __align__(16) float g_O [(size_t)BNUM*NTOK*EMB];
__device__ __align__(16) float g_Bi[NHEAD*WD*WD];     // 19208 floats

// ---------------------------------------------------------------------------
__global__ __launch_bounds__(512) void bias_kernel(const float* __restrict__ rpb) {
    int i = blockIdx.x * 512 + threadIdx.x;
    if (i >= NHEAD*WD*WD) return;
    int h  = i / (WD*WD);
    int r2 = i - h*(WD*WD);
    int a  = r2 / WD;
    int bb = r2 - a*WD;
    int idx = (a/7 - bb/7 + 6)*13 + (a%7 - bb%7 + 6);
    g_Bi[i] = rpb[idx*NHEAD + h];
}

// ---------------------------------------------------------------------------
__device__ __forceinline__ unsigned f2tf32(float f) {
    unsigned r;
    asm("cvt.rna.tf32.f32 %0, %1;" : "=r"(r) : "f"(f));
    return r;
}

__device__ __forceinline__ void mma_tf32(float* c, unsigned a0, unsigned a1,
                                         unsigned a2, unsigned a3,
                                         unsigned b0, unsigned b1) {
    asm volatile(
        "mma.sync.aligned.m16n8k8.row.col.f32.tf32.tf32.f32 "
        "{%0,%1,%2,%3}, {%4,%5,%6,%7}, {%8,%9}, {%0,%1,%2,%3};\n"
        : "+f"(c[0]), "+f"(c[1]), "+f"(c[2]), "+f"(c[3])
        : "r"(a0), "r"(a1), "r"(a2), "r"(a3), "r"(b0), "r"(b1));
}

// ---------------------------------------------------------------------------
// Fused kernel smem layout (floats):
//   Ks @ 0      : 8 heads x 32 d-rows x stride 60 (j, zero-padded)   = 15360
//   Vs @ 15360  : 8 heads x 56 j-rows x stride 40 (d, zero-padded)   = 17920
//   X  @ 33280  : 49 tokens x stride 260 (fp32 shifted window)        = 12740
//   Ws @ 46020  : 32 k x stride 104 (tf32 bits)                       = 3328
//   bs @ 49348  : 96 (fp32)
//   Rg @ 49444  : 64 ints
//   total 49508 floats = 198,032 B  (1 block/SM, 512 thr, 16 warps)
// ---------------------------------------------------------------------------
#define OFF_KS 0
#define KS_H   1920
#define OFF_VS 15360
#define VS_H   2240
#define OFF_X  33280
#define XS     260
#define OFF_WS 46020
#define WS_S   104
#define OFF_BS 49348
#define OFF_RG 49444
#define SMEM_FLOATS 49508

__global__ __launch_bounds__(512) void fused_kernel(const float* __restrict__ x,
                                                    const float* __restrict__ Wq,
                                                    const float* __restrict__ bq) {
    extern __shared__ float sm[];
    float* X  = sm + OFF_X;
    float* bs = sm + OFF_BS;
    int*   Rg = reinterpret_cast<int*>(sm + OFF_RG);
    unsigned* Wsu = reinterpret_cast<unsigned*>(sm + OFF_WS);

    int bw = blockIdx.x;
    int b  = bw >> 6, w = bw & 63;
    int wr = w >> 3,  wc = w & 7;
    int tid = threadIdx.x, warp = tid >> 5, lane = tid & 31;
    int g = lane >> 2, t = lane & 3;
    int h = warp >> 1, p = warp & 1;
    int m0_0 = p ? 17 : 0;
    int m0_1 = p ? 33 : 16;

    // zero K/V regions (covers j/d padding)
    {
        float4* z = reinterpret_cast<float4*>(sm);
        for (int i = tid; i < (OFF_VS + 17920)/4; i += 512) z[i] = make_float4(0,0,0,0);
    }
    // stage qkv weights as tf32, bias fp32
    for (int i = tid; i < 32*96; i += 512) {
        int k = i / 96, n = i - k*96;
        Wsu[k*WS_S + n] = f2tf32(Wq[i]);
    }
    if (tid < 96) bs[tid] = bq[tid];
    if (tid < WD) {
        int rs = wr*7 + tid/7, cs = wc*7 + tid%7;
        int zr = (rs < 49) ? 0 : ((rs < 53) ? 1 : 2);
        int zc = (cs < 49) ? 0 : ((cs < 53) ? 1 : 2);
        Rg[tid] = zr*3 + zc;
    }
    // stage shifted x window (fp32, padded stride 260)
    {
        const float4* x4 = reinterpret_cast<const float4*>(x);
        float4* xs4 = reinterpret_cast<float4*>(X);
        for (int i = tid; i < WD*64; i += 512) {
            int tk = i >> 6, qq = i & 63;
            int tr = tk / 7, tc = tk - tr*7;
            int row = wr*7 + tr + 3; if (row >= HW) row -= HW;
            int col = wc*7 + tc + 3; if (col >= HW) col -= HW;
            xs4[tk*65 + qq] = x4[((size_t)b*NTOK + row*HW + col)*64 + qq];
        }
    }
    __syncthreads();

    // ---- QKV projection via mma: A = X (rows of this warp's 2 m-tiles) ----
    unsigned a_[2][4][4];
    int hc = h*HDIM;
#pragma unroll
    for (int mi = 0; mi < 2; ++mi) {
        int m0 = mi ? m0_1 : m0_0;
#pragma unroll
        for (int ks = 0; ks < 4; ++ks) {
            int k0 = ks*8;
            a_[mi][ks][0] = f2tf32(X[(m0+g  )*XS + hc + k0 + t    ]);
            a_[mi][ks][1] = f2tf32(X[(m0+g+8)*XS + hc + k0 + t    ]);
            a_[mi][ks][2] = f2tf32(X[(m0+g  )*XS + hc + k0 + t + 4]);
            a_[mi][ks][3] = f2tf32(X[(m0+g+8)*XS + hc + k0 + t + 4]);
        }
    }

    // Q pass (cols 0..31) -> frags (scaled, tf32)
    unsigned qu[2][4][4];
    const float qscale = 0.17677669529663687f;
#pragma unroll
    for (int mi = 0; mi < 2; ++mi) {
#pragma unroll
        for (int nt = 0; nt < 4; ++nt) {
            float c4[4] = {0.f,0.f,0.f,0.f};
#pragma unroll
            for (int ks = 0; ks < 4; ++ks) {
                int k0 = ks*8;
                unsigned b0 = Wsu[(k0+t  )*WS_S + nt*8 + g];
                unsigned b1 = Wsu[(k0+t+4)*WS_S + nt*8 + g];
                mma_tf32(c4, a_[mi][ks][0],a_[mi][ks][1],a_[mi][ks][2],a_[mi][ks][3], b0,b1);
            }
            int d0 = nt*8 + 2*t;
            qu[mi][nt][0] = f2tf32((c4[0] + bs[d0  ]) * qscale);
            qu[mi][nt][1] = f2tf32((c4[1] + bs[d0+1]) * qscale);
            qu[mi][nt][2] = f2tf32((c4[2] + bs[d0  ]) * qscale);
            qu[mi][nt][3] = f2tf32((c4[3] + bs[d0+1]) * qscale);
        }
    }
    // K pass (cols 32..63) -> Ks[d][row] transposed tf32
    {
        unsigned* Kh = reinterpret_cast<unsigned*>(sm + OFF_KS) + h*KS_H;
#pragma unroll
        for (int mi = 0; mi < 2; ++mi) {
            int m0 = mi ? m0_1 : m0_0;
#pragma unroll
            for (int nt = 0; nt < 4; ++nt) {
                float c4[4] = {0.f,0.f,0.f,0.f};
#pragma unroll
                for (int ks = 0; ks < 4; ++ks) {
                    int k0 = ks*8;
                    unsigned b0 = Wsu[(k0+t  )*WS_S + 32 + nt*8 + g];
                    unsigned b1 = Wsu[(k0+t+4)*WS_S + 32 + nt*8 + g];
                    mma_tf32(c4, a_[mi][ks][0],a_[mi][ks][1],a_[mi][ks][2],a_[mi][ks][3], b0,b1);
                }
                int d0 = nt*8 + 2*t;
                Kh[(d0  )*60 + m0+g  ] = f2tf32(c4[0] + bs[32+d0  ]);
                Kh[(d0+1)*60 + m0+g  ] = f2tf32(c4[1] + bs[32+d0+1]);
                Kh[(d0  )*60 + m0+g+8] = f2tf32(c4[2] + bs[32+d0  ]);
                Kh[(d0+1)*60 + m0+g+8] = f2tf32(c4[3] + bs[32+d0+1]);
            }
        }
    }
    // V pass (cols 64..95) -> Vs[row][d] tf32
    {
        unsigned* Vh = reinterpret_cast<unsigned*>(sm + OFF_VS) + h*VS_H;
#pragma unroll
        for (int mi = 0; mi < 2; ++mi) {
            int m0 = mi ? m0_1 : m0_0;
#pragma unroll
            for (int nt = 0; nt < 4; ++nt) {
                float c4[4] = {0.f,0.f,0.f,0.f};
#pragma unroll
                for (int ks = 0; ks < 4; ++ks) {
                    int k0 = ks*8;
                    unsigned b0 = Wsu[(k0+t  )*WS_S + 64 + nt*8 + g];
                    unsigned b1 = Wsu[(k0+t+4)*WS_S + 64 + nt*8 + g];
                    mma_tf32(c4, a_[mi][ks][0],a_[mi][ks][1],a_[mi][ks][2],a_[mi][ks][3], b0,b1);
                }
                int d0 = nt*8 + 2*t;
                Vh[(m0+g  )*40 + d0  ] = f2tf32(c4[0] + bs[64+d0  ]);
                Vh[(m0+g  )*40 + d0+1] = f2tf32(c4[1] + bs[64+d0+1]);
                Vh[(m0+g+8)*40 + d0  ] = f2tf32(c4[2] + bs[64+d0  ]);
                Vh[(m0+g+8)*40 + d0+1] = f2tf32(c4[3] + bs[64+d0+1]);
            }
        }
    }

    // rearrange Q c-frags -> a-frags via warp shuffles (warp-local, pre-sync ok)
    int src0 = (g << 2) | (t >> 1);
    unsigned qa[2][4][4];
#pragma unroll
    for (int mi = 0; mi < 2; ++mi)
#pragma unroll
        for (int ks = 0; ks < 4; ++ks) {
            unsigned v00 = __shfl_sync(0xffffffffu, qu[mi][ks][0], src0);
            unsigned v01 = __shfl_sync(0xffffffffu, qu[mi][ks][1], src0);
            unsigned v02 = __shfl_sync(0xffffffffu, qu[mi][ks][2], src0);
            unsigned v03 = __shfl_sync(0xffffffffu, qu[mi][ks][3], src0);
            unsigned v10 = __shfl_sync(0xffffffffu, qu[mi][ks][0], src0+2);
            unsigned v11 = __shfl_sync(0xffffffffu, qu[mi][ks][1], src0+2);
            unsigned v12 = __shfl_sync(0xffffffffu, qu[mi][ks][2], src0+2);
            unsigned v13 = __shfl_sync(0xffffffffu, qu[mi][ks][3], src0+2);
            bool odd = (t & 1);
            qa[mi][ks][0] = odd ? v01 : v00;
            qa[mi][ks][1] = odd ? v03 : v02;
            qa[mi][ks][2] = odd ? v11 : v10;
            qa[mi][ks][3] = odd ? v13 : v12;
        }

    __syncthreads();   // K/V from both warps of each head visible

    // ---- scores: S[i][j] = Q · K^T  (M=2x16 tiles, N=7x8 tiles, K=4x8) ----
    float s[2][7][4];
#pragma unroll
    for (int mi = 0; mi < 2; ++mi)
#pragma unroll
        for (int nt = 0; nt < 7; ++nt)
            s[mi][nt][0]=s[mi][nt][1]=s[mi][nt][2]=s[mi][nt][3]=0.f;
    {
        const unsigned* Kh = reinterpret_cast<const unsigned*>(sm + OFF_KS) + h*KS_H;
#pragma unroll
        for (int ks = 0; ks < 4; ++ks) {
            int k0 = ks*8;
#pragma unroll
            for (int nt = 0; nt < 7; ++nt) {
                unsigned b0 = Kh[(k0+t  )*60 + nt*8 + g];
                unsigned b1 = Kh[(k0+t+4)*60 + nt*8 + g];
                mma_tf32(s[0][nt], qa[0][ks][0],qa[0][ks][1],qa[0][ks][2],qa[0][ks][3], b0,b1);
                mma_tf32(s[1][nt], qa[1][ks][0],qa[1][ks][1],qa[1][ks][2],qa[1][ks][3], b0,b1);
            }
        }
    }

    // ---- softmax (single pass; full row spread over the 4-lane quad) ----
    int row0[2] = {m0_0 + g, m0_1 + g};
    float inv_l[2][2];
    int rgj[7][2];
#pragma unroll
    for (int nt = 0; nt < 7; ++nt) {
        int j0 = nt*8 + 2*t;
        rgj[nt][0] = (j0   < WD) ? Rg[j0]   : -1;
        rgj[nt][1] = (j0+1 < WD) ? Rg[j0+1] : -1;
    }
    const float* Bh = g_Bi + h*(WD*WD);
#pragma unroll
    for (int mi = 0; mi < 2; ++mi) {
#pragma unroll
        for (int half = 0; half < 2; ++half) {
            int i = row0[mi] + half*8;
            int myrg = Rg[i];
            float mx = -1e30f;
#pragma unroll
            for (int nt = 0; nt < 7; ++nt) {
#pragma unroll
                for (int c = 0; c < 2; ++c) {
                    int j = nt*8 + 2*t + c;
                    float v;
                    if (j < WD)
                        v = s[mi][nt][half*2+c] + __ldg(Bh + i*WD + j)
                          + ((rgj[nt][c] == myrg) ? 0.f : -100.f);
                    else v = -1e30f;
                    s[mi][nt][half*2+c] = v;
                    mx = fmaxf(mx, v);
                }
            }
            mx = fmaxf(mx, __shfl_xor_sync(0xffffffffu, mx, 1));
            mx = fmaxf(mx, __shfl_xor_sync(0xffffffffu, mx, 2));
            float l = 0.f;
#pragma unroll
            for (int nt = 0; nt < 7; ++nt)
#pragma unroll
                for (int c = 0; c < 2; ++c) {
                    float e = __expf(s[mi][nt][half*2+c] - mx);
                    s[mi][nt][half*2+c] = e;
                    l += e;
                }
            l += __shfl_xor_sync(0xffffffffu, l, 1);
            l += __shfl_xor_sync(0xffffffffu, l, 2);
            inv_l[mi][half] = 1.f / l;
        }
    }
    // convert P to tf32 bits in place
#pragma unroll
    for (int mi = 0; mi < 2; ++mi)
#pragma unroll
        for (int nt = 0; nt < 7; ++nt)
#pragma unroll
            for (int c = 0; c < 4; ++c)
                s[mi][nt][c] = __uint_as_float(f2tf32(s[mi][nt][c]));

    // ---- PV: O[i][d] = P · V  (K = 7x8 steps over j; pad p==0, V padded 0) ----
    float o[2][4][4];
#pragma unroll
    for (int mi = 0; mi < 2; ++mi)
#pragma unroll
        for (int nt = 0; nt < 4; ++nt)
            o[mi][nt][0]=o[mi][nt][1]=o[mi][nt][2]=o[mi][nt][3]=0.f;
    {
        const unsigned* Vh = reinterpret_cast<const unsigned*>(sm + OFF_VS) + h*VS_H;
#pragma unroll
        for (int ks = 0; ks < 7; ++ks) {
            int k0 = ks*8;
            unsigned pa[2][4];
#pragma unroll
            for (int mi = 0; mi < 2; ++mi) {
                float v00 = __shfl_sync(0xffffffffu, s[mi][ks][0], src0);
                float v01 = __shfl_sync(0xffffffffu, s[mi][ks][1], src0);
                float v02 = __shfl_sync(0xffffffffu, s[mi][ks][2], src0);
                float v03 = __shfl_sync(0xffffffffu, s[mi][ks][3], src0);
                float v10 = __shfl_sync(0xffffffffu, s[mi][ks][0], src0+2);
                float v11 = __shfl_sync(0xffffffffu, s[mi][ks][1], src0+2);
                float v12 = __shfl_sync(0xffffffffu, s[mi][ks][2], src0+2);
                float v13 = __shfl_sync(0xffffffffu, s[mi][ks][3], src0+2);
                bool odd = (t & 1);
                pa[mi][0] = __float_as_uint(odd ? v01 : v00);
                pa[mi][1] = __float_as_uint(odd ? v03 : v02);
                pa[mi][2] = __float_as_uint(odd ? v11 : v10);
                pa[mi][3] = __float_as_uint(odd ? v13 : v12);
            }
#pragma unroll
            for (int nt = 0; nt < 4; ++nt) {
                unsigned b0 = Vh[(k0+t  )*40 + nt*8 + g];
                unsigned b1 = Vh[(k0+t+4)*40 + nt*8 + g];
                mma_tf32(o[0][nt], pa[0][0],pa[0][1],pa[0][2],pa[0][3], b0,b1);
                mma_tf32(o[1][nt], pa[1][0],pa[1][1],pa[1][2],pa[1][3], b0,b1);
            }
        }
    }

    // ---- scatter output (reverse shift); duplicate rows write same bits ----
#pragma unroll
    for (int mi = 0; mi < 2; ++mi)
#pragma unroll
        for (int half = 0; half < 2; ++half) {
            int i = row0[mi] + half*8;
            int tr = i/7, tc = i - tr*7;
            int rs = wr*7 + tr + 3; if (rs >= HW) rs -= HW;
            int cs = wc*7 + tc + 3; if (cs >= HW) cs -= HW;
            float inv = inv_l[mi][half];
            float* dst = g_O + ((size_t)b*NTOK + rs*HW + cs)*EMB + h*HDIM;
#pragma unroll
            for (int nt = 0; nt < 4; ++nt) {
                float2 v;
                v.x = o[mi][nt][half*2+0] * inv;
                v.y = o[mi][nt][half*2+1] * inv;
                *reinterpret_cast<float2*>(dst + nt*8 + 2*t) = v;
            }
        }
}

// ---------------------------------------------------------------------------
// Kernel C: output projection GEMM (unchanged, TF32 MMA).
// ---------------------------------------------------------------------------
__global__ __launch_bounds__(256) void proj_kernel(const float* __restrict__ Wp,
                                                   const float* __restrict__ bp,
                                                   float* __restrict__ out) {
    __shared__ unsigned As[32][136];
    __shared__ unsigned Bs[32][136];

    int bm = blockIdx.x;
    int bn = blockIdx.y;
    int tid = threadIdx.x;
    int warp = tid >> 5, lane = tid & 31;
    int g = lane >> 2, t = lane & 3;

    int wm = (warp & 1) * 64;
    int wn = (warp >> 1) * 32;

    float acc[4][4][4];
#pragma unroll
    for (int mi = 0; mi < 4; ++mi)
#pragma unroll
        for (int ni = 0; ni < 4; ++ni)
#pragma unroll
            for (int rr = 0; rr < 4; ++rr) acc[mi][ni][rr] = 0.f;

    const float* Ag = g_O + (size_t)bm * 128 * EMB;
    int ar = tid >> 1, ac = (tid & 1) * 16;
    int br = tid >> 3, bc = (tid & 7) * 16;

    for (int kb = 0; kb < EMB; kb += 32) {
#pragma unroll
        for (int i = 0; i < 4; ++i) {
            float4 v = *reinterpret_cast<const float4*>(Ag + (size_t)ar*EMB + kb + ac + i*4);
            As[ac + i*4 + 0][ar] = f2tf32(v.x);
            As[ac + i*4 + 1][ar] = f2tf32(v.y);
            As[ac + i*4 + 2][ar] = f2tf32(v.z);
            As[ac + i*4 + 3][ar] = f2tf32(v.w);
        }
#pragma unroll
        for (int i = 0; i < 4; ++i) {
            float4 v = *reinterpret_cast<const float4*>(Wp + (size_t)(kb + br)*EMB + bn*128 + bc + i*4);
            uint4 u;
            u.x = f2tf32(v.x); u.y = f2tf32(v.y);
            u.z = f2tf32(v.z); u.w = f2tf32(v.w);
            *reinterpret_cast<uint4*>(&Bs[br][bc + i*4]) = u;
        }
        __syncthreads();

#pragma unroll
        for (int ks = 0; ks < 4; ++ks) {
            int k0 = ks * 8;
            unsigned af[4][4];
#pragma unroll
            for (int mi = 0; mi < 4; ++mi) {
                int m0 = wm + mi*16;
                af[mi][0] = As[k0 + t    ][m0 + g    ];
                af[mi][1] = As[k0 + t    ][m0 + g + 8];
                af[mi][2] = As[k0 + t + 4][m0 + g    ];
                af[mi][3] = As[k0 + t + 4][m0 + g + 8];
            }
            unsigned bf[4][2];
#pragma unroll
            for (int ni = 0; ni < 4; ++ni) {
                int n0 = wn + ni*8;
                bf[ni][0] = Bs[k0 + t    ][n0 + g];
                bf[ni][1] = Bs[k0 + t + 4][n0 + g];
            }
#pragma unroll
            for (int mi = 0; mi < 4; ++mi)
#pragma unroll
                for (int ni = 0; ni < 4; ++ni)
                    mma_tf32(acc[mi][ni], af[mi][0], af[mi][1], af[mi][2], af[mi][3],
                             bf[ni][0], bf[ni][1]);
        }
        __syncthreads();
    }

#pragma unroll
    for (int ni = 0; ni < 4; ++ni) {
        int n = bn*128 + wn + ni*8 + 2*t;
        float2 bb = *reinterpret_cast<const float2*>(bp + n);
#pragma unroll
        for (int mi = 0; mi < 4; ++mi) {
            size_t m = (size_t)bm*128 + wm + mi*16;
            float2 v0, v1;
            v0.x = acc[mi][ni][0] + bb.x; v0.y = acc[mi][ni][1] + bb.y;
            v1.x = acc[mi][ni][2] + bb.x; v1.y = acc[mi][ni][3] + bb.y;
            *reinterpret_cast<float2*>(out + (m + g    )*EMB + n) = v0;
            *reinterpret_cast<float2*>(out + (m + g + 8)*EMB + n) = v1;
        }
    }
}

// ---------------------------------------------------------------------------
extern "C" void kernel_launch(void* const* d_in, const int* in_sizes, int n_in,
                              void* d_out, int out_size) {
    const float* x      = (const float*)d_in[0];
    const float* qkv_w  = (const float*)d_in[1];
    const float* qkv_b  = (const float*)d_in[2];
    const float* proj_w = (const float*)d_in[3];
    const float* proj_b = (const float*)d_in[4];
    const float* rpb    = (const float*)d_in[5];
    float* out = (float*)d_out;

    const int fused_smem = SMEM_FLOATS * 4;    // 198,032 B
    cudaFuncSetAttribute(fused_kernel, cudaFuncAttributeMaxDynamicSharedMemorySize, fused_smem);

    bias_kernel<<<(NHEAD*WD*WD + 511)/512, 512>>>(rpb);
    fused_kernel<<<BNUM*NWIN, 512, fused_smem>>>(x, qkv_w, qkv_b);
    dim3 grid(BNUM*NTOK/128, EMB/128);
    proj_kernel<<<grid, 256>>>(proj_w, proj_b, out);
}

// round 9
// speedup vs baseline: 2.6064x; 1.1085x over previous
#include <cuda_runtime.h>

// ---------------------------------------------------------------------------
// SWMSA: shifted-window multi-head self-attention (Swin block attention)
// B=32, H=W=56, WS=7, SS=3, NH=8, E=256, HD=32, NW=64, WD=49
// Kernel A: one-shot rel-pos-bias expansion
// Kernel B: tensor-core fused QKV + attention; block = (window, 4 heads),
//           256 threads, 73.6KB smem -> 2 blocks/SM for latency overlap
// Kernel C: output projection GEMM [TF32 MMA]
// ---------------------------------------------------------------------------

#define BNUM 32
#define HW   56
#define NHEAD 8
#define EMB  256
#define HDIM 32
#define NWIN 64
#define WD   49
#define NTOK (HW*HW)              // 3136

__device__ __align__(16) float g_O [(size_t)BNUM*NTOK*EMB];
__device__ __align__(16) float g_Bi[NHEAD*WD*WD];     // 19208 floats

// ---------------------------------------------------------------------------
__global__ __launch_bounds__(512) void bias_kernel(const float* __restrict__ rpb) {
    int i = blockIdx.x * 512 + threadIdx.x;
    if (i >= NHEAD*WD*WD) return;
    int h  = i / (WD*WD);
    int r2 = i - h*(WD*WD);
    int a  = r2 / WD;
    int bb = r2 - a*WD;
    int idx = (a/7 - bb/7 + 6)*13 + (a%7 - bb%7 + 6);
    g_Bi[i] = rpb[idx*NHEAD + h];
}

// ---------------------------------------------------------------------------
__device__ __forceinline__ unsigned f2tf32(float f) {
    unsigned r;
    asm("cvt.rna.tf32.f32 %0, %1;" : "=r"(r) : "f"(f));
    return r;
}

__device__ __forceinline__ void mma_tf32(float* c, unsigned a0, unsigned a1,
                                         unsigned a2, unsigned a3,
                                         unsigned b0, unsigned b1) {
    asm volatile(
        "mma.sync.aligned.m16n8k8.row.col.f32.tf32.tf32.f32 "
        "{%0,%1,%2,%3}, {%4,%5,%6,%7}, {%8,%9}, {%0,%1,%2,%3};\n"
        : "+f"(c[0]), "+f"(c[1]), "+f"(c[2]), "+f"(c[3])
        : "r"(a0), "r"(a1), "r"(a2), "r"(a3), "r"(b0), "r"(b1));
}

// ---------------------------------------------------------------------------
// Fused kernel smem layout (floats), block = 4 heads of one window:
//   Ks  @ 0     : 4 heads x 32 d-rows x 56 j  (tf32 bits)   = 7168
//   Vs  @ 7168  : 4 heads x 32 d-rows x 60 j  (tf32, zeroed)= 7680
//   Ws  @ 14848 : 32 k x stride 104 (tf32 bits)             = 3328
//   bs  @ 18176 : 96 (fp32)
//   Rg  @ 18272 : 64 ints (shift-region ids)
//   gof @ 18336 : 64 ints (token -> global element offset)
//   total 18400 floats = 73,600 B  -> 2 blocks/SM (256 thr, <=128 regs)
// ---------------------------------------------------------------------------
#define OFF_KS 0
#define KS_H   1792      // 32*56
#define OFF_VS 7168
#define VS_H   1920      // 32*60
#define OFF_WS 14848
#define WS_S   104
#define OFF_BS 18176
#define OFF_RG 18272
#define OFF_GO 18336
#define SMEM_FLOATS 18400

__global__ __launch_bounds__(256, 2) void fused_kernel(const float* __restrict__ x,
                                                       const float* __restrict__ Wq,
                                                       const float* __restrict__ bq) {
    extern __shared__ float sm[];
    float* bs = sm + OFF_BS;
    int*   Rg  = reinterpret_cast<int*>(sm + OFF_RG);
    int*   gof = reinterpret_cast<int*>(sm + OFF_GO);
    unsigned* Wsu = reinterpret_cast<unsigned*>(sm + OFF_WS);

    int bw2 = blockIdx.x;
    int hg = bw2 & 1, bw = bw2 >> 1;
    int b  = bw >> 6, w = bw & 63;
    int wr = w >> 3,  wc = w & 7;
    int tid = threadIdx.x, warp = tid >> 5, lane = tid & 31;
    int g = lane >> 2, t = lane & 3;
    int lh = warp >> 1, p = warp & 1;
    int h = hg*4 + lh;
    int m0_0 = p ? 17 : 0;
    int m0_1 = p ? 33 : 16;

    // zero Vs (pad j columns must be exact 0 for PV)
    {
        float4* z = reinterpret_cast<float4*>(sm + OFF_VS);
        for (int i = tid; i < 7680/4; i += 256) z[i] = make_float4(0,0,0,0);
    }
    // stage qkv weights as tf32, bias fp32
    for (int i = tid; i < 32*96; i += 256) {
        int k = i / 96, n = i - k*96;
        Wsu[k*WS_S + n] = f2tf32(Wq[i]);
    }
    if (tid < 96) bs[tid] = bq[tid];
    if (tid < WD) {
        int tr = tid/7, tc = tid - 7*(tid/7);
        int rs = wr*7 + tr, cs = wc*7 + tc;          // shifted-grid coords
        int zr = (rs < 49) ? 0 : ((rs < 53) ? 1 : 2);
        int zc = (cs < 49) ? 0 : ((cs < 53) ? 1 : 2);
        Rg[tid] = zr*3 + zc;
        int row = rs + 3; if (row >= HW) row -= HW;  // original-grid coords
        int col = cs + 3; if (col >= HW) col -= HW;
        gof[tid] = (b*NTOK + row*HW + col)*EMB;
    }
    __syncthreads();

    // ---- A-frags (x rows, this head's 32-col slice) direct from global ----
    unsigned a_[2][4][4];
    int hc = h*HDIM;
#pragma unroll
    for (int mi = 0; mi < 2; ++mi) {
        int m0 = mi ? m0_1 : m0_0;
        int r0 = gof[m0+g] + hc;
        int r1 = gof[m0+g+8] + hc;
#pragma unroll
        for (int ks = 0; ks < 4; ++ks) {
            int k0 = ks*8;
            a_[mi][ks][0] = f2tf32(__ldg(x + r0 + k0 + t    ));
            a_[mi][ks][1] = f2tf32(__ldg(x + r1 + k0 + t    ));
            a_[mi][ks][2] = f2tf32(__ldg(x + r0 + k0 + t + 4));
            a_[mi][ks][3] = f2tf32(__ldg(x + r1 + k0 + t + 4));
        }
    }

    // ---- Q pass (cols 0..31) -> frags (scaled, tf32) ----
    unsigned qu[2][4][4];
    const float qscale = 0.17677669529663687f;
#pragma unroll
    for (int mi = 0; mi < 2; ++mi) {
#pragma unroll
        for (int nt = 0; nt < 4; ++nt) {
            float c4[4] = {0.f,0.f,0.f,0.f};
#pragma unroll
            for (int ks = 0; ks < 4; ++ks) {
                int k0 = ks*8;
                unsigned b0 = Wsu[(k0+t  )*WS_S + nt*8 + g];
                unsigned b1 = Wsu[(k0+t+4)*WS_S + nt*8 + g];
                mma_tf32(c4, a_[mi][ks][0],a_[mi][ks][1],a_[mi][ks][2],a_[mi][ks][3], b0,b1);
            }
            int d0 = nt*8 + 2*t;
            qu[mi][nt][0] = f2tf32((c4[0] + bs[d0  ]) * qscale);
            qu[mi][nt][1] = f2tf32((c4[1] + bs[d0+1]) * qscale);
            qu[mi][nt][2] = f2tf32((c4[2] + bs[d0  ]) * qscale);
            qu[mi][nt][3] = f2tf32((c4[3] + bs[d0+1]) * qscale);
        }
    }
    // ---- K pass (cols 32..63) -> Ks[d][j] stride 56 ----
    {
        unsigned* Kh = reinterpret_cast<unsigned*>(sm + OFF_KS) + lh*KS_H;
#pragma unroll
        for (int mi = 0; mi < 2; ++mi) {
            int m0 = mi ? m0_1 : m0_0;
#pragma unroll
            for (int nt = 0; nt < 4; ++nt) {
                float c4[4] = {0.f,0.f,0.f,0.f};
#pragma unroll
                for (int ks = 0; ks < 4; ++ks) {
                    int k0 = ks*8;
                    unsigned b0 = Wsu[(k0+t  )*WS_S + 32 + nt*8 + g];
                    unsigned b1 = Wsu[(k0+t+4)*WS_S + 32 + nt*8 + g];
                    mma_tf32(c4, a_[mi][ks][0],a_[mi][ks][1],a_[mi][ks][2],a_[mi][ks][3], b0,b1);
                }
                int d0 = nt*8 + 2*t;
                Kh[(d0  )*56 + m0+g  ] = f2tf32(c4[0] + bs[32+d0  ]);
                Kh[(d0+1)*56 + m0+g  ] = f2tf32(c4[1] + bs[32+d0+1]);
                Kh[(d0  )*56 + m0+g+8] = f2tf32(c4[2] + bs[32+d0  ]);
                Kh[(d0+1)*56 + m0+g+8] = f2tf32(c4[3] + bs[32+d0+1]);
            }
        }
    }
    // ---- V pass (cols 64..95) -> Vs[d][j] stride 60 (transposed) ----
    {
        unsigned* Vh = reinterpret_cast<unsigned*>(sm + OFF_VS) + lh*VS_H;
#pragma unroll
        for (int mi = 0; mi < 2; ++mi) {
            int m0 = mi ? m0_1 : m0_0;
#pragma unroll
            for (int nt = 0; nt < 4; ++nt) {
                float c4[4] = {0.f,0.f,0.f,0.f};
#pragma unroll
                for (int ks = 0; ks < 4; ++ks) {
                    int k0 = ks*8;
                    unsigned b0 = Wsu[(k0+t  )*WS_S + 64 + nt*8 + g];
                    unsigned b1 = Wsu[(k0+t+4)*WS_S + 64 + nt*8 + g];
                    mma_tf32(c4, a_[mi][ks][0],a_[mi][ks][1],a_[mi][ks][2],a_[mi][ks][3], b0,b1);
                }
                int d0 = nt*8 + 2*t;
                Vh[(d0  )*60 + m0+g  ] = f2tf32(c4[0] + bs[64+d0  ]);
                Vh[(d0+1)*60 + m0+g  ] = f2tf32(c4[1] + bs[64+d0+1]);
                Vh[(d0  )*60 + m0+g+8] = f2tf32(c4[2] + bs[64+d0  ]);
                Vh[(d0+1)*60 + m0+g+8] = f2tf32(c4[3] + bs[64+d0+1]);
            }
        }
    }

    // rearrange Q c-frags -> a-frags via warp shuffles (warp-local, pre-sync ok)
    int src0 = (g << 2) | (t >> 1);
    unsigned qa[2][4][4];
#pragma unroll
    for (int mi = 0; mi < 2; ++mi)
#pragma unroll
        for (int ks = 0; ks < 4; ++ks) {
            unsigned v00 = __shfl_sync(0xffffffffu, qu[mi][ks][0], src0);
            unsigned v01 = __shfl_sync(0xffffffffu, qu[mi][ks][1], src0);
            unsigned v02 = __shfl_sync(0xffffffffu, qu[mi][ks][2], src0);
            unsigned v03 = __shfl_sync(0xffffffffu, qu[mi][ks][3], src0);
            unsigned v10 = __shfl_sync(0xffffffffu, qu[mi][ks][0], src0+2);
            unsigned v11 = __shfl_sync(0xffffffffu, qu[mi][ks][1], src0+2);
            unsigned v12 = __shfl_sync(0xffffffffu, qu[mi][ks][2], src0+2);
            unsigned v13 = __shfl_sync(0xffffffffu, qu[mi][ks][3], src0+2);
            bool odd = (t & 1);
            qa[mi][ks][0] = odd ? v01 : v00;
            qa[mi][ks][1] = odd ? v03 : v02;
            qa[mi][ks][2] = odd ? v11 : v10;
            qa[mi][ks][3] = odd ? v13 : v12;
        }

    __syncthreads();   // K/V from both warps of each head visible

    // ---- scores: S = Q · K^T ----
    float s[2][7][4];
#pragma unroll
    for (int mi = 0; mi < 2; ++mi)
#pragma unroll
        for (int nt = 0; nt < 7; ++nt)
            s[mi][nt][0]=s[mi][nt][1]=s[mi][nt][2]=s[mi][nt][3]=0.f;
    {
        const unsigned* Kh = reinterpret_cast<const unsigned*>(sm + OFF_KS) + lh*KS_H;
#pragma unroll
        for (int ks = 0; ks < 4; ++ks) {
            int k0 = ks*8;
#pragma unroll
            for (int nt = 0; nt < 7; ++nt) {
                unsigned b0 = Kh[(k0+t  )*56 + nt*8 + g];
                unsigned b1 = Kh[(k0+t+4)*56 + nt*8 + g];
                mma_tf32(s[0][nt], qa[0][ks][0],qa[0][ks][1],qa[0][ks][2],qa[0][ks][3], b0,b1);
                mma_tf32(s[1][nt], qa[1][ks][0],qa[1][ks][1],qa[1][ks][2],qa[1][ks][3], b0,b1);
            }
        }
    }

    // ---- softmax (single pass; full row over the 4-lane quad) ----
    int row0[2] = {m0_0 + g, m0_1 + g};
    float inv_l[2][2];
    int rgj[7][2];
#pragma unroll
    for (int nt = 0; nt < 7; ++nt) {
        int j0 = nt*8 + 2*t;
        rgj[nt][0] = (j0   < WD) ? Rg[j0]   : -1;
        rgj[nt][1] = (j0+1 < WD) ? Rg[j0+1] : -1;
    }
    const float* Bh = g_Bi + h*(WD*WD);
#pragma unroll
    for (int mi = 0; mi < 2; ++mi) {
#pragma unroll
        for (int half = 0; half < 2; ++half) {
            int i = row0[mi] + half*8;
            int myrg = Rg[i];
            float mx = -1e30f;
#pragma unroll
            for (int nt = 0; nt < 7; ++nt) {
#pragma unroll
                for (int c = 0; c < 2; ++c) {
                    int j = nt*8 + 2*t + c;
                    float v;
                    if (j < WD)
                        v = s[mi][nt][half*2+c] + __ldg(Bh + i*WD + j)
                          + ((rgj[nt][c] == myrg) ? 0.f : -100.f);
                    else v = -1e30f;
                    s[mi][nt][half*2+c] = v;
                    mx = fmaxf(mx, v);
                }
            }
            mx = fmaxf(mx, __shfl_xor_sync(0xffffffffu, mx, 1));
            mx = fmaxf(mx, __shfl_xor_sync(0xffffffffu, mx, 2));
            float l = 0.f;
#pragma unroll
            for (int nt = 0; nt < 7; ++nt)
#pragma unroll
                for (int c = 0; c < 2; ++c) {
                    float e = __expf(s[mi][nt][half*2+c] - mx);
                    s[mi][nt][half*2+c] = e;
                    l += e;
                }
            l += __shfl_xor_sync(0xffffffffu, l, 1);
            l += __shfl_xor_sync(0xffffffffu, l, 2);
            inv_l[mi][half] = 1.f / l;
        }
    }
    // convert P to tf32 bits in place
#pragma unroll
    for (int mi = 0; mi < 2; ++mi)
#pragma unroll
        for (int nt = 0; nt < 7; ++nt)
#pragma unroll
            for (int c = 0; c < 4; ++c)
                s[mi][nt][c] = __uint_as_float(f2tf32(s[mi][nt][c]));

    // ---- PV: O = P · V  (V stored [d][j]: B[k=j][n=d] = Vh[n*60 + k]) ----
    float o[2][4][4];
#pragma unroll
    for (int mi = 0; mi < 2; ++mi)
#pragma unroll
        for (int nt = 0; nt < 4; ++nt)
            o[mi][nt][0]=o[mi][nt][1]=o[mi][nt][2]=o[mi][nt][3]=0.f;
    {
        const unsigned* Vh = reinterpret_cast<const unsigned*>(sm + OFF_VS) + lh*VS_H;
#pragma unroll
        for (int ks = 0; ks < 7; ++ks) {
            int k0 = ks*8;
            unsigned pa[2][4];
#pragma unroll
            for (int mi = 0; mi < 2; ++mi) {
                float v00 = __shfl_sync(0xffffffffu, s[mi][ks][0], src0);
                float v01 = __shfl_sync(0xffffffffu, s[mi][ks][1], src0);
                float v02 = __shfl_sync(0xffffffffu, s[mi][ks][2], src0);
                float v03 = __shfl_sync(0xffffffffu, s[mi][ks][3], src0);
                float v10 = __shfl_sync(0xffffffffu, s[mi][ks][0], src0+2);
                float v11 = __shfl_sync(0xffffffffu, s[mi][ks][1], src0+2);
                float v12 = __shfl_sync(0xffffffffu, s[mi][ks][2], src0+2);
                float v13 = __shfl_sync(0xffffffffu, s[mi][ks][3], src0+2);
                bool odd = (t & 1);
                pa[mi][0] = __float_as_uint(odd ? v01 : v00);
                pa[mi][1] = __float_as_uint(odd ? v03 : v02);
                pa[mi][2] = __float_as_uint(odd ? v11 : v10);
                pa[mi][3] = __float_as_uint(odd ? v13 : v12);
            }
#pragma unroll
            for (int nt = 0; nt < 4; ++nt) {
                unsigned b0 = Vh[(nt*8+g)*60 + k0+t  ];
                unsigned b1 = Vh[(nt*8+g)*60 + k0+t+4];
                mma_tf32(o[0][nt], pa[0][0],pa[0][1],pa[0][2],pa[0][3], b0,b1);
                mma_tf32(o[1][nt], pa[1][0],pa[1][1],pa[1][2],pa[1][3], b0,b1);
            }
        }
    }

    // ---- scatter output (reverse shift via gof); duplicate rows same bits ----
#pragma unroll
    for (int mi = 0; mi < 2; ++mi)
#pragma unroll
        for (int half = 0; half < 2; ++half) {
            int i = row0[mi] + half*8;
            float inv = inv_l[mi][half];
            float* dst = g_O + gof[i] + hc;
#pragma unroll
            for (int nt = 0; nt < 4; ++nt) {
                float2 v;
                v.x = o[mi][nt][half*2+0] * inv;
                v.y = o[mi][nt][half*2+1] * inv;
                *reinterpret_cast<float2*>(dst + nt*8 + 2*t) = v;
            }
        }
}

// ---------------------------------------------------------------------------
// Kernel C: output projection GEMM (unchanged, TF32 MMA).
// ---------------------------------------------------------------------------
__global__ __launch_bounds__(256) void proj_kernel(const float* __restrict__ Wp,
                                                   const float* __restrict__ bp,
                                                   float* __restrict__ out) {
    __shared__ unsigned As[32][136];
    __shared__ unsigned Bs[32][136];

    int bm = blockIdx.x;
    int bn = blockIdx.y;
    int tid = threadIdx.x;
    int warp = tid >> 5, lane = tid & 31;
    int g = lane >> 2, t = lane & 3;

    int wm = (warp & 1) * 64;
    int wn = (warp >> 1) * 32;

    float acc[4][4][4];
#pragma unroll
    for (int mi = 0; mi < 4; ++mi)
#pragma unroll
        for (int ni = 0; ni < 4; ++ni)
#pragma unroll
            for (int rr = 0; rr < 4; ++rr) acc[mi][ni][rr] = 0.f;

    const float* Ag = g_O + (size_t)bm * 128 * EMB;
    int ar = tid >> 1, ac = (tid & 1) * 16;
    int br = tid >> 3, bc = (tid & 7) * 16;

    for (int kb = 0; kb < EMB; kb += 32) {
#pragma unroll
        for (int i = 0; i < 4; ++i) {
            float4 v = *reinterpret_cast<const float4*>(Ag + (size_t)ar*EMB + kb + ac + i*4);
            As[ac + i*4 + 0][ar] = f2tf32(v.x);
            As[ac + i*4 + 1][ar] = f2tf32(v.y);
            As[ac + i*4 + 2][ar] = f2tf32(v.z);
            As[ac + i*4 + 3][ar] = f2tf32(v.w);
        }
#pragma unroll
        for (int i = 0; i < 4; ++i) {
            float4 v = *reinterpret_cast<const float4*>(Wp + (size_t)(kb + br)*EMB + bn*128 + bc + i*4);
            uint4 u;
            u.x = f2tf32(v.x); u.y = f2tf32(v.y);
            u.z = f2tf32(v.z); u.w = f2tf32(v.w);
            *reinterpret_cast<uint4*>(&Bs[br][bc + i*4]) = u;
        }
        __syncthreads();

#pragma unroll
        for (int ks = 0; ks < 4; ++ks) {
            int k0 = ks * 8;
            unsigned af[4][4];
#pragma unroll
            for (int mi = 0; mi < 4; ++mi) {
                int m0 = wm + mi*16;
                af[mi][0] = As[k0 + t    ][m0 + g    ];
                af[mi][1] = As[k0 + t    ][m0 + g + 8];
                af[mi][2] = As[k0 + t + 4][m0 + g    ];
                af[mi][3] = As[k0 + t + 4][m0 + g + 8];
            }
            unsigned bf[4][2];
#pragma unroll
            for (int ni = 0; ni < 4; ++ni) {
                int n0 = wn + ni*8;
                bf[ni][0] = Bs[k0 + t    ][n0 + g];
                bf[ni][1] = Bs[k0 + t + 4][n0 + g];
            }
#pragma unroll
            for (int mi = 0; mi < 4; ++mi)
#pragma unroll
                for (int ni = 0; ni < 4; ++ni)
                    mma_tf32(acc[mi][ni], af[mi][0], af[mi][1], af[mi][2], af[mi][3],
                             bf[ni][0], bf[ni][1]);
        }
        __syncthreads();
    }

#pragma unroll
    for (int ni = 0; ni < 4; ++ni) {
        int n = bn*128 + wn + ni*8 + 2*t;
        float2 bb = *reinterpret_cast<const float2*>(bp + n);
#pragma unroll
        for (int mi = 0; mi < 4; ++mi) {
            size_t m = (size_t)bm*128 + wm + mi*16;
            float2 v0, v1;
            v0.x = acc[mi][ni][0] + bb.x; v0.y = acc[mi][ni][1] + bb.y;
            v1.x = acc[mi][ni][2] + bb.x; v1.y = acc[mi][ni][3] + bb.y;
            *reinterpret_cast<float2*>(out + (m + g    )*EMB + n) = v0;
            *reinterpret_cast<float2*>(out + (m + g + 8)*EMB + n) = v1;
        }
    }
}

// ---------------------------------------------------------------------------
extern "C" void kernel_launch(void* const* d_in, const int* in_sizes, int n_in,
                              void* d_out, int out_size) {
    const float* x      = (const float*)d_in[0];
    const float* qkv_w  = (const float*)d_in[1];
    const float* qkv_b  = (const float*)d_in[2];
    const float* proj_w = (const float*)d_in[3];
    const float* proj_b = (const float*)d_in[4];
    const float* rpb    = (const float*)d_in[5];
    float* out = (float*)d_out;

    const int fused_smem = SMEM_FLOATS * 4;    // 73,600 B
    cudaFuncSetAttribute(fused_kernel, cudaFuncAttributeMaxDynamicSharedMemorySize, fused_smem);

    bias_kernel<<<(NHEAD*WD*WD + 511)/512, 512>>>(rpb);
    fused_kernel<<<BNUM*NWIN*2, 256, fused_smem>>>(x, qkv_w, qkv_b);
    dim3 grid(BNUM*NTOK/128, EMB/128);
    proj_kernel<<<grid, 256>>>(proj_w, proj_b, out);
}